// round 1
// baseline (speedup 1.0000x reference)
#include <cuda_runtime.h>

// BrockHommes: B=8192 independent rows, T=4096 sequential steps each.
// One thread per row; latency-bound recurrence. Prefetch eps as float4 at
// distance 2; write out as float4.

#define B_CONST 8192
#define T_CONST 4096

__device__ __forceinline__ float ex2a(float x) {
    float y;
    asm("ex2.approx.f32 %0, %1;" : "=f"(y) : "f"(x));
    return y;
}
__device__ __forceinline__ float rcpa(float x) {
    float y;
    asm("rcp.approx.f32 %0, %1;" : "=f"(y) : "f"(x));
    return y;
}

__global__ void __launch_bounds__(64, 1)
bh_kernel(const float* __restrict__ theta,
          const float* __restrict__ eps,
          float* __restrict__ out)
{
    int b = blockIdx.x * 64 + threadIdx.x;
    if (b >= B_CONST) return;

    const float* th = theta + b * 11;
    const float beta = th[0];
    const float g0 = th[1], g1 = th[2], g2 = th[3], g3 = th[4];
    const float b0 = th[5], b1 = th[6], b2 = th[7], b3 = th[8];
    const float sigma = th[9];
    const float r = th[10];

    const float R    = 1.0f + r;
    const float invR = 1.0f / R;              // one-time accurate div
    const float bl   = beta * 1.44269504088896340736f;  // beta * log2(e)
    const float sigR = sigma * invR;

    const float4* ep4 = reinterpret_cast<const float4*>(eps + (size_t)b * T_CONST);
    float4*       o4  = reinterpret_cast<float4*>(out + (size_t)b * T_CONST);
    const int T4 = T_CONST / 4;

    float x1 = 0.0f, x2 = 0.0f, x3 = 0.0f;

    // distance-2 prefetch pipeline for eps
    float4 buf0 = ep4[0];
    float4 buf1 = ep4[1];

    for (int i = 0; i < T4; ++i) {
        float4 ev = buf0;
        buf0 = buf1;
        if (i + 2 < T4) buf1 = ep4[i + 2];

        float eo[4] = {ev.x, ev.y, ev.z, ev.w};
        float xo[4];

        #pragma unroll
        for (int k = 0; k < 4; ++k) {
            // --- off-critical-path terms (depend on x2/x3, available early) ---
            float Rx2  = R * x2;
            float nbl2 = bl * Rx2;                       // bl * R * x2
            float c0 = fmaf(g0, x3, b0 - Rx2);
            float c1 = fmaf(g1, x3, b1 - Rx2);
            float c2 = fmaf(g2, x3, b2 - Rx2);
            float c3 = fmaf(g3, x3, b3 - Rx2);

            // --- critical path: depends on x1 ---
            float sL = fmaf(bl, x1, -nbl2);              // beta*log2e*(x1 - R*x2)
            float t0 = sL * c0;
            float t1 = sL * c1;
            float t2 = sL * c2;
            float t3 = sL * c3;

            // softmax (log2 domain) with max-subtraction for overflow safety
            float M  = fmaxf(fmaxf(t0, t1), fmaxf(t2, t3));
            float p0 = ex2a(t0 - M);
            float p1 = ex2a(t1 - M);
            float p2 = ex2a(t2 - M);
            float p3 = ex2a(t3 - M);

            float m0 = fmaf(g0, x1, b0);
            float m1 = fmaf(g1, x1, b1);
            float m2 = fmaf(g2, x1, b2);
            float m3 = fmaf(g3, x1, b3);

            float den = (p0 + p1) + (p2 + p3);           // in [1,4] after max-sub
            float num = fmaf(p1, m1, p0 * m0) + fmaf(p3, m3, p2 * m2);

            // fast reciprocal + one Newton step (~1 ulp)
            float rd = rcpa(den);
            rd = rd * (2.0f - den * rd);

            float xt = fmaf(num * rd, invR, eo[k] * sigR);

            x3 = x2; x2 = x1; x1 = xt;
            xo[k] = xt;
        }

        o4[i] = make_float4(xo[0], xo[1], xo[2], xo[3]);
    }
}

extern "C" void kernel_launch(void* const* d_in, const int* in_sizes, int n_in,
                              void* d_out, int out_size)
{
    const float* theta = (const float*)d_in[0];   // (B, 11) float32
    const float* eps   = (const float*)d_in[1];   // (B, T)  float32
    float*       out   = (float*)d_out;           // (B, T)  float32

    bh_kernel<<<B_CONST / 64, 64>>>(theta, eps, out);
}